// round 9
// baseline (speedup 1.0000x reference)
#include <cuda_runtime.h>

// ---------------------------------------------------------------------------
// BoxCrossCategoryLoss, round 5 (resubmit after infra failure): pure scalar +
// convex-max relu grouping:
//   sum_i relu(S - x_i) over sorted x1<=x2<=x3
//     = max(0, S-x1, 2S-(x1+x2), 3S-(x1+x2+x3))
// Subtrahend sets are shared across 5 S's each -> sort cost amortized.
// log2-domain math, fused NEG-recipe log1mexp forms, fused last-block
// reduction. rel_id inputs are dead.
// ---------------------------------------------------------------------------

#define GRID_BLOCKS 1184   // 8 * 148 SMs
#define NTHREADS 256

__device__ float        g_partials[GRID_BLOCKS];
__device__ unsigned int g_ctr = 0;

__device__ __forceinline__ float ex2f_(float x) {
    float r; asm("ex2.approx.f32 %0, %1;" : "=f"(r) : "f"(x)); return r;
}
__device__ __forceinline__ float lg2f_(float x) {
    float r; asm("lg2.approx.f32 %0, %1;" : "=f"(r) : "f"(x)); return r;
}

// sum of relu(S - xi) over a sorted triple, as max of chords
__device__ __forceinline__ float grp3(float S, float x1, float n12, float n123) {
    float t1 = S - x1;
    float t2 = __fmaf_rn(S, 2.0f, n12);    // 2S - (x1+x2)   (FFMA-imm, rt 1)
    float t3 = __fmaf_rn(S, 3.0f, n123);   // 3S - (x1+x2+x3)
    return fmaxf(fmaxf(t1, t2), fmaxf(t3, 0.0f));
}
// sum of relu(S - xi) over a sorted pair
__device__ __forceinline__ float grp2(float S, float x1, float n12) {
    float t1 = S - x1;
    float t2 = __fmaf_rn(S, 2.0f, n12);
    return fmaxf(fmaxf(t1, t2), 0.0f);
}

// One element; 12 inputs already scaled to log2 units.
__device__ __forceinline__ void elem_loss(
    float ab0, float ab1, float ba0, float ba1,
    float bc0, float bc1, float cb0, float cb1,
    float ac0, float ac1, float ca0, float ca1,
    float& q0, float& q1, float& q2, float& q3)
{
    // 2^x for all 12 inputs
    float eab0 = ex2f_(ab0), eab1 = ex2f_(ab1);
    float eba0 = ex2f_(ba0), eba1 = ex2f_(ba1);
    float ebc0 = ex2f_(bc0), ebc1 = ex2f_(bc1);
    float ecb0 = ex2f_(cb0), ecb1 = ex2f_(cb1);
    float eac0 = ex2f_(ac0), eac1 = ex2f_(ac1);
    float eca0 = ex2f_(ca0), eca1 = ex2f_(ca1);

    // 1 - 2^x
    float sab0 = 1.0f - eab0, sab1 = 1.0f - eab1;
    float sba0 = 1.0f - eba0, sba1 = 1.0f - eba1;
    float sbc0 = 1.0f - ebc0, sbc1 = 1.0f - ebc1;
    float scb0 = 1.0f - ecb0, scb1 = 1.0f - ecb1;
    float sac0 = 1.0f - eac0, sac1 = 1.0f - eac1;
    float sca0 = 1.0f - eca0, sca1 = 1.0f - eca1;

    // log2(1 - 2^x) where individually needed
    float Lab0 = lg2f_(sab0), Lab1 = lg2f_(sab1);
    float Lba0 = lg2f_(sba0), Lba1 = lg2f_(sba1);
    float Lbc0 = lg2f_(sbc0), Lbc1 = lg2f_(sbc1);
    float Lcb0 = lg2f_(scb0), Lcb1 = lg2f_(scb1);
    float ACla1 = lg2f_(sac1), AClb1 = lg2f_(sca1);

    // AC col0 fused log1mexp(prob) forms
    float w  = eac0 * eca0;
    float L0 = lg2f_(sac0 + w);        // log2(1 - ua(1-ub))
    float L1 = lg2f_(sca0 + w);        // log2(1 - (1-ua)ub)
    float L2 = lg2f_(1.0f - w);        // log2(1 - ua*ub)

    // probability logs
    float A0x = ab0 + Lba0, A1x = Lab0 + ba0, A2x = ab0 + ba0;
    float A0y = ab1 + Lba1, A1y = Lab1 + ba1, A2y = ab1 + ba1;
    float A3y = Lab1 + Lba1;
    float B0x = bc0 + Lcb0, B1x = Lbc0 + cb0, B2x = bc0 + cb0;
    float B0y = bc1 + Lcb1, B1y = Lbc1 + cb1, B2y = bc1 + cb1;
    float B3y = Lbc1 + Lcb1;
    float AC0 = ac1 + AClb1, AC1 = ACla1 + ca1;
    float AC2 = ac1 + ca1,   AC3 = ACla1 + AClb1;

    // --- group 1: X = {AC0, L1, L2}, sorted ---
    float g1lo = fminf(AC0, L1), g1hi = fmaxf(AC0, L1);
    float g1x3 = fmaxf(g1hi, L2), g1mid = fminf(g1hi, L2);
    float g1x1 = fminf(g1lo, g1mid), g1x2 = fmaxf(g1lo, g1mid);
    float g1n12  = (-g1x1) - g1x2;
    float g1n123 = g1n12 - g1x3;

    // --- group 2: X = {AC1, L0, L2}, sorted ---
    float g2lo = fminf(AC1, L0), g2hi = fmaxf(AC1, L0);
    float g2x3 = fmaxf(g2hi, L2), g2mid = fminf(g2hi, L2);
    float g2x1 = fminf(g2lo, g2mid), g2x2 = fmaxf(g2lo, g2mid);
    float g2n12  = (-g2x1) - g2x2;
    float g2n123 = g2n12 - g2x3;

    // --- group 4: X = {AC3, L2}, sorted ---
    float g4x1 = fminf(AC3, L2);
    float g4n12 = (-AC3) - L2;

    // group-1 S's
    q0 += grp3(A0x + B0y, g1x1, g1n12, g1n123);   // S1
    q1 += grp3(A0x + B2y, g1x1, g1n12, g1n123);   // S2
    q2 += grp3(A2x + B0y, g1x1, g1n12, g1n123);   // S5
    q3 += grp3(A0y + B0x, g1x1, g1n12, g1n123);   // S9
    q0 += grp3(A0y + B2x, g1x1, g1n12, g1n123);   // S10
    // group-2 S's
    q1 += grp3(A1x + B1y, g2x1, g2n12, g2n123);   // S3
    q2 += grp3(A1x + B2y, g2x1, g2n12, g2n123);   // S4
    q3 += grp3(A2x + B1y, g2x1, g2n12, g2n123);   // S6
    q0 += grp3(A1y + B1x, g2x1, g2n12, g2n123);   // S11
    q1 += grp3(A1y + B2x, g2x1, g2n12, g2n123);   // S12
    // group-3 (single X = AC2)
    q2 += fmaxf((A2x + B2y) - AC2, 0.0f);          // S7
    q3 += fmaxf((A2y + B2x) - AC2, 0.0f);          // S13
    // group-4
    q0 += grp2(A2x + B3y, g4x1, g4n12);            // S8
    q1 += grp2(A3y + B2x, g4x1, g4n12);            // S14
}

__global__ void __launch_bounds__(NTHREADS)
loss_kernel(const float* __restrict__ AB, const float* __restrict__ BA,
            const float* __restrict__ BC, const float* __restrict__ CB,
            const float* __restrict__ AC, const float* __restrict__ CA,
            int n_elems, float* __restrict__ out)
{
    constexpr float K = 1.44269504088896340736f;  // log2(e)
    const float4* AB4 = (const float4*)AB;
    const float4* BA4 = (const float4*)BA;
    const float4* BC4 = (const float4*)BC;
    const float4* CB4 = (const float4*)CB;
    const float4* AC4 = (const float4*)AC;
    const float4* CA4 = (const float4*)CA;

    int n4 = n_elems >> 1;   // one float4 per array covers 2 elements
    float q0 = 0.0f, q1 = 0.0f, q2 = 0.0f, q3 = 0.0f;

    for (int j = blockIdx.x * NTHREADS + threadIdx.x; j < n4;
         j += GRID_BLOCKS * NTHREADS) {
        float4 vab = AB4[j], vba = BA4[j];
        float4 vbc = BC4[j], vcb = CB4[j];
        float4 vac = AC4[j], vca = CA4[j];

        elem_loss(vab.x * K, vab.y * K, vba.x * K, vba.y * K,
                  vbc.x * K, vbc.y * K, vcb.x * K, vcb.y * K,
                  vac.x * K, vac.y * K, vca.x * K, vca.y * K,
                  q0, q1, q2, q3);
        elem_loss(vab.z * K, vab.w * K, vba.z * K, vba.w * K,
                  vbc.z * K, vbc.w * K, vcb.z * K, vcb.w * K,
                  vac.z * K, vac.w * K, vca.z * K, vca.w * K,
                  q0, q1, q2, q3);
    }

    // odd tail (not hit for N = 8M)
    if ((n_elems & 1) && blockIdx.x == 0 && threadIdx.x == 0) {
        int i = n_elems - 1;
        elem_loss(AB[2*i] * K, AB[2*i+1] * K, BA[2*i] * K, BA[2*i+1] * K,
                  BC[2*i] * K, BC[2*i+1] * K, CB[2*i] * K, CB[2*i+1] * K,
                  AC[2*i] * K, AC[2*i+1] * K, CA[2*i] * K, CA[2*i+1] * K,
                  q0, q1, q2, q3);
    }

    float acc = (q0 + q1) + (q2 + q3);

    #pragma unroll
    for (int o = 16; o > 0; o >>= 1)
        acc += __shfl_xor_sync(0xFFFFFFFFu, acc, o);

    __shared__ float ws[NTHREADS / 32];
    __shared__ bool  amLast;
    if ((threadIdx.x & 31) == 0) ws[threadIdx.x >> 5] = acc;
    __syncthreads();
    if (threadIdx.x == 0) {
        float s = 0.0f;
        #pragma unroll
        for (int i = 0; i < NTHREADS / 32; i++) s += ws[i];
        g_partials[blockIdx.x] = s;
        __threadfence();
        unsigned old = atomicInc(&g_ctr, GRID_BLOCKS - 1);  // wraps to 0
        amLast = (old == GRID_BLOCKS - 1);
    }
    __syncthreads();

    if (amLast) {
        __shared__ double sh[NTHREADS];
        double s = 0.0;
        for (int i = threadIdx.x; i < GRID_BLOCKS; i += NTHREADS)
            s += (double)__ldcg(&g_partials[i]);
        sh[threadIdx.x] = s;
        __syncthreads();
        #pragma unroll
        for (int st = NTHREADS / 2; st > 0; st >>= 1) {
            if (threadIdx.x < st) sh[threadIdx.x] += sh[threadIdx.x + st];
            __syncthreads();
        }
        if (threadIdx.x == 0)
            out[0] = (float)(sh[0] * 0.69314718055994530942);  // log2 -> nat
    }
}

extern "C" void kernel_launch(void* const* d_in, const int* in_sizes, int n_in,
                              void* d_out, int out_size)
{
    const float* AB = (const float*)d_in[0];
    const float* BA = (const float*)d_in[1];
    const float* BC = (const float*)d_in[2];
    const float* CB = (const float*)d_in[3];
    const float* AC = (const float*)d_in[4];
    const float* CA = (const float*)d_in[5];
    // d_in[6..8] (xy/yz/xz rel_id) are dead inputs in the reference.

    int n_elems = in_sizes[0] / 2;

    loss_kernel<<<GRID_BLOCKS, NTHREADS>>>(AB, BA, BC, CB, AC, CA, n_elems,
                                           (float*)d_out);
}